// round 3
// baseline (speedup 1.0000x reference)
#include <cuda_runtime.h>
#include <math.h>

#define B 128
#define T 1024
#define H 256
#define G4 1024   // 4*H

// ------------------- device scratch (static, zero-initialized) -------------------
__device__ float g_xp[(size_t)2 * T * B * G4];     // x@Wih.T + b, rows reordered (4*h+gate), [d][t][b][1024]
__device__ float g_hstore[(size_t)2 * T * B * H];  // recorded h, [d][t][b][h]
__device__ float g_WT[2 * H * G4];                 // Whh transposed+reordered: [d][k][r']
__device__ float g_outWT[512 * 32];                // out_W transposed: [k][j]
__device__ float g_hbuf[2 * 2 * B * H];            // ping-pong h state: [parity][d][b][h]
__device__ float g_c[2 * B * H];                   // cell state: [d][b][h]
__device__ float g_af[B * 32];                     // addr_feat
__device__ float g_scores[B * T];
__device__ int   g_cnt[16];                        // per-(dir,btile) step counters

// ------------------- clear state (per replay) -------------------
__global__ void clear_kernel() {
    int i = blockIdx.x * 256 + threadIdx.x;
    if (i < 2 * 2 * B * H) g_hbuf[i] = 0.0f;
    if (i < 2 * B * H)     g_c[i]    = 0.0f;
    if (i < 16)            g_cnt[i]  = 0;
}

// ------------------- weight prep: transpose + gate-interleave -------------------
__global__ void prep_kernel(const float* __restrict__ Whh_f,
                            const float* __restrict__ Whh_b,
                            const float* __restrict__ out_W) {
    int idx = blockIdx.x * 256 + threadIdx.x;
    if (idx < 2 * H * G4) {
        int rp = idx & 1023;           // reordered row r' = 4*jh + g
        int k  = (idx >> 10) & 255;    // Whh column (h index)
        int d  = idx >> 18;
        int g  = rp & 3, jh = rp >> 2;
        const float* Whh = d ? Whh_b : Whh_f;
        g_WT[idx] = Whh[(g * 256 + jh) * H + k];
    }
    if (idx < 512 * 32) {
        int k = idx >> 5, j = idx & 31;
        g_outWT[idx] = out_W[j * 512 + k];
    }
}

// ------------------- addr_feat -------------------
__global__ void addr_kernel(const float* __restrict__ addr,
                            const int*   __restrict__ addr_type,
                            const float* __restrict__ poi_emb,
                            const float* __restrict__ addr_W,
                            const float* __restrict__ addr_b) {
    int b = threadIdx.x;  // 128
    float inp[4];
    inp[0] = addr[b];
    int at = addr_type[b];
    inp[1] = poi_emb[at * 3 + 0];
    inp[2] = poi_emb[at * 3 + 1];
    inp[3] = poi_emb[at * 3 + 2];
    for (int j = 0; j < 32; j++) {
        float a = addr_b[j];
        #pragma unroll
        for (int f = 0; f < 4; f++) a += addr_W[j * 4 + f] * inp[f];
        g_af[b * 32 + j] = a;
    }
}

// ------------------- xp = loc_seq @ Wih.T + b (reordered rows), active (b,t) only -------------------
__global__ void __launch_bounds__(256) xp_kernel(
    const float* __restrict__ loc_dense, const float* __restrict__ time_dist,
    const int* __restrict__ len, const float* __restrict__ time_W,
    const float* __restrict__ time_b,
    const float* __restrict__ Wih_f, const float* __restrict__ b_f,
    const float* __restrict__ Wih_b, const float* __restrict__ b_b) {
    int b = blockIdx.y, d = blockIdx.z;
    int t0 = blockIdx.x * 32;
    int n = len[b];
    if (t0 >= n) return;
    const float* Wih  = d ? Wih_b : Wih_f;
    const float* bias = d ? b_b  : b_f;

    __shared__ float loc19[32][19];
    int tid = threadIdx.x;
    for (int i = tid; i < 32 * 16; i += 256) {
        int tt = i >> 4, f = i & 15;
        loc19[tt][f] = loc_dense[((size_t)b * T + t0 + tt) * 16 + f];
    }
    if (tid < 96) {
        int tt = tid / 3, e = tid % 3;
        float acc = time_b[e];
        const float* tdp = &time_dist[((size_t)b * T + t0 + tt) * 8];
        #pragma unroll
        for (int f = 0; f < 8; f++) acc += time_W[e * 8 + f] * tdp[f];
        loc19[tt][16 + e] = acc;
    }
    __syncthreads();

    int j = tid;  // h index 0..255; owns reordered rows 4j..4j+3
    float w[4][19], bz[4];
    #pragma unroll
    for (int g = 0; g < 4; g++) {
        int orig = g * 256 + j;
        bz[g] = bias[orig];
        #pragma unroll
        for (int f = 0; f < 19; f++) w[g][f] = Wih[orig * 19 + f];
    }
    int tmax = min(32, n - t0);
    for (int tt = 0; tt < tmax; tt++) {
        float accs[4];
        #pragma unroll
        for (int g = 0; g < 4; g++) {
            float a = bz[g];
            #pragma unroll
            for (int f = 0; f < 19; f++) a += w[g][f] * loc19[tt][f];
            accs[g] = a;
        }
        float4 out4 = make_float4(accs[0], accs[1], accs[2], accs[3]);
        *(float4*)&g_xp[(((size_t)d * T + t0 + tt) * B + b) * G4 + j * 4] = out4;
    }
}

// ------------------- persistent bidirectional LSTM recurrence -------------------
// Grid (8 gate-tiles, 8 batch-tiles, 2 dirs) = 128 CTAs, all co-resident (<=148 SMs).
// Each CTA: 128 reordered gate rows x 16 batches, Whh tile resident in smem.
// Group = 8 CTAs sharing (btile, dir); sync via monotonic counter in g_cnt.
__global__ void __launch_bounds__(256, 1) lstm_kernel(const int* __restrict__ len) {
    extern __shared__ float smem[];
    float* sW  = smem;                    // [256][128]  128 KB
    float* h_s = smem + 256 * 128;        // [256][20]   20 KB (padded)
    float* pre = h_s + 256 * 20;          // [128][17]   8.7 KB

    int gx  = blockIdx.x;   // gate tile (128 reordered rows)
    int gy  = blockIdx.y;   // batch tile (16 batches)
    int dir = blockIdx.z;
    int tid = threadIdx.x;
    int b0  = gy * 16;
    int h0  = gx * 32;
    int nloc = len[b0];     // tile max length (sorted descending)
    int* cnt = &g_cnt[dir * 8 + gy];

    // resident weight tile: sW[k][row] = WT[d][k][gx*128+row]
    const float* WT = &g_WT[(size_t)dir * H * G4 + gx * 128];
    for (int e = tid; e < 256 * 128; e += 256) {
        int k = e >> 7, row = e & 127;
        sW[k * 128 + row] = WT[(size_t)k * G4 + row];
    }
    __syncthreads();

    int tx = tid & 127;   // row local
    int ty = tid >> 7;    // batch half (8 batches each)

    for (int i = 0; i < nloc; i++) {
        int s = dir ? (nloc - 1 - i) : i;
        int pin = i & 1, pout = pin ^ 1;

        if (i > 0) {
            if (tid == 0) {
                while (atomicAdd(cnt, 0) < 8 * i) { }
            }
            __syncthreads();
        }

        // load h(t-1) for this batch tile (bypass L1: written by peer SMs)
        const float* hg = &g_hbuf[((size_t)(pin * 2 + dir) * B + b0) * H];
        #pragma unroll
        for (int p = 0; p < 16; p++) {
            int e = tid + 256 * p;
            int k = e & 255, bl = e >> 8;
            h_s[k * 20 + bl] = __ldcg(&hg[(size_t)bl * H + k]);
        }
        __syncthreads();

        float a0 = 0.f, a1 = 0.f, a2 = 0.f, a3 = 0.f;
        float a4 = 0.f, a5 = 0.f, a6 = 0.f, a7 = 0.f;
        #pragma unroll 4
        for (int k = 0; k < 256; k++) {
            float wv = sW[k * 128 + tx];
            float4 ha = *(const float4*)&h_s[k * 20 + ty * 8];
            float4 hb = *(const float4*)&h_s[k * 20 + ty * 8 + 4];
            a0 = fmaf(wv, ha.x, a0);
            a1 = fmaf(wv, ha.y, a1);
            a2 = fmaf(wv, ha.z, a2);
            a3 = fmaf(wv, ha.w, a3);
            a4 = fmaf(wv, hb.x, a4);
            a5 = fmaf(wv, hb.y, a5);
            a6 = fmaf(wv, hb.z, a6);
            a7 = fmaf(wv, hb.w, a7);
        }

        // add precomputed x-projection (includes bias), stage for epilogue
        size_t xbase = (((size_t)dir * T + s) * B + b0 + ty * 8) * G4 + gx * 128 + tx;
        pre[tx * 17 + ty * 8 + 0] = a0 + g_xp[xbase + 0 * (size_t)G4];
        pre[tx * 17 + ty * 8 + 1] = a1 + g_xp[xbase + 1 * (size_t)G4];
        pre[tx * 17 + ty * 8 + 2] = a2 + g_xp[xbase + 2 * (size_t)G4];
        pre[tx * 17 + ty * 8 + 3] = a3 + g_xp[xbase + 3 * (size_t)G4];
        pre[tx * 17 + ty * 8 + 4] = a4 + g_xp[xbase + 4 * (size_t)G4];
        pre[tx * 17 + ty * 8 + 5] = a5 + g_xp[xbase + 5 * (size_t)G4];
        pre[tx * 17 + ty * 8 + 6] = a6 + g_xp[xbase + 6 * (size_t)G4];
        pre[tx * 17 + ty * 8 + 7] = a7 + g_xp[xbase + 7 * (size_t)G4];
        __syncthreads();

        // epilogue: 32 h x 16 b = 512 outputs, 2 per thread
        #pragma unroll
        for (int q = 0; q < 2; q++) {
            int o  = tid + q * 256;
            int hl = o & 31, b2 = o >> 5;
            int b  = b0 + b2;
            size_t ho = ((size_t)(pout * 2 + dir) * B + b) * H + h0 + hl;
            if (s < len[b]) {
                float gi = pre[(4 * hl + 0) * 17 + b2];
                float gf = pre[(4 * hl + 1) * 17 + b2];
                float gg = pre[(4 * hl + 2) * 17 + b2];
                float go = pre[(4 * hl + 3) * 17 + b2];
                size_t ci = ((size_t)dir * B + b) * H + h0 + hl;
                float cold = g_c[ci];
                float si = 1.f / (1.f + expf(-gi));
                float sf = 1.f / (1.f + expf(-gf));
                float so = 1.f / (1.f + expf(-go));
                float cn = sf * cold + si * tanhf(gg);
                float hn = so * tanhf(cn);
                g_c[ci] = cn;
                g_hbuf[ho] = hn;
                g_hstore[(((size_t)dir * T + s) * B + b) * H + h0 + hl] = hn;
            } else {
                g_hbuf[ho] = h_s[(h0 + hl) * 20 + b2];  // carry forward
            }
        }
        __threadfence();
        __syncthreads();
        if (tid == 0) atomicAdd(cnt, 1);
    }
}

// ------------------- scores: comb_W . tanh(out_W @ [hf;hb] + addr_feat) -------------------
__global__ void __launch_bounds__(256) score_kernel(const int* __restrict__ len,
                                                    const float* __restrict__ comb_W) {
    int b = blockIdx.y;
    int t0 = blockIdx.x * 8;
    int n = len[b];
    if (t0 >= n) return;
    int w = threadIdx.x >> 5, lane = threadIdx.x & 31;
    int t = t0 + w;
    if (t >= n) return;
    float a0 = g_af[b * 32 + lane], a1 = 0.f, a2 = 0.f, a3 = 0.f;
    const float* hf = &g_hstore[(((size_t)0 * T + t) * B + b) * H];
    const float* hb = &g_hstore[(((size_t)1 * T + t) * B + b) * H];
    #pragma unroll 8
    for (int k = 0; k < 256; k += 4) {
        float4 h4 = *(const float4*)&hf[k];
        a0 = fmaf(g_outWT[(k + 0) * 32 + lane], h4.x, a0);
        a1 = fmaf(g_outWT[(k + 1) * 32 + lane], h4.y, a1);
        a2 = fmaf(g_outWT[(k + 2) * 32 + lane], h4.z, a2);
        a3 = fmaf(g_outWT[(k + 3) * 32 + lane], h4.w, a3);
    }
    #pragma unroll 8
    for (int k = 0; k < 256; k += 4) {
        float4 h4 = *(const float4*)&hb[k];
        a0 = fmaf(g_outWT[(256 + k + 0) * 32 + lane], h4.x, a0);
        a1 = fmaf(g_outWT[(256 + k + 1) * 32 + lane], h4.y, a1);
        a2 = fmaf(g_outWT[(256 + k + 2) * 32 + lane], h4.z, a2);
        a3 = fmaf(g_outWT[(256 + k + 3) * 32 + lane], h4.w, a3);
    }
    float v = tanhf(a0 + a1 + a2 + a3) * comb_W[lane];
    #pragma unroll
    for (int off = 16; off; off >>= 1) v += __shfl_down_sync(0xffffffffu, v, off);
    if (lane == 0) g_scores[b * T + t] = v;
}

// ------------------- masked log-softmax over T -------------------
__global__ void __launch_bounds__(256) softmax_kernel(const int* __restrict__ len,
                                                      float* __restrict__ out) {
    int b = blockIdx.x;
    int n = len[b];
    int tid = threadIdx.x;
    __shared__ float red[256];
    float m = -1e30f;
    for (int t = tid; t < n; t += 256) m = fmaxf(m, g_scores[b * T + t]);
    red[tid] = m; __syncthreads();
    for (int st = 128; st; st >>= 1) {
        if (tid < st) red[tid] = fmaxf(red[tid], red[tid + st]);
        __syncthreads();
    }
    m = red[0]; __syncthreads();
    float sum = 0.f;
    for (int t = tid; t < n; t += 256) sum += expf(g_scores[b * T + t] - m);
    red[tid] = sum; __syncthreads();
    for (int st = 128; st; st >>= 1) {
        if (tid < st) red[tid] += red[tid + st];
        __syncthreads();
    }
    float lse = m + logf(red[0]);
    for (int t = tid; t < T; t += 256)
        out[b * T + t] = (t < n) ? (g_scores[b * T + t] - lse) : 0.0f;
}

// ------------------- launch -------------------
extern "C" void kernel_launch(void* const* d_in, const int* in_sizes, int n_in,
                              void* d_out, int out_size) {
    (void)in_sizes; (void)n_in; (void)out_size;
    const float* addr      = (const float*)d_in[0];
    const int*   addr_type = (const int*)  d_in[1];
    const float* loc_dense = (const float*)d_in[2];
    const float* time_dist = (const float*)d_in[3];
    const int*   len       = (const int*)  d_in[4];
    const float* poi_emb   = (const float*)d_in[5];
    const float* time_W    = (const float*)d_in[6];
    const float* time_b    = (const float*)d_in[7];
    const float* addr_W    = (const float*)d_in[8];
    const float* addr_b    = (const float*)d_in[9];
    const float* Wih_f     = (const float*)d_in[10];
    const float* Whh_f     = (const float*)d_in[11];
    const float* b_f       = (const float*)d_in[12];
    const float* Wih_b     = (const float*)d_in[13];
    const float* Whh_b     = (const float*)d_in[14];
    const float* b_b       = (const float*)d_in[15];
    const float* out_W     = (const float*)d_in[16];
    const float* comb_W    = (const float*)d_in[17];
    float* out = (float*)d_out;

    static int smem_set = 0;
    const int LSTM_SMEM = (256 * 128 + 256 * 20 + 128 * 17) * 4;  // 160256 B
    if (!smem_set) {
        cudaFuncSetAttribute(lstm_kernel,
                             cudaFuncAttributeMaxDynamicSharedMemorySize, LSTM_SMEM);
        smem_set = 1;
    }

    clear_kernel<<<512, 256>>>();
    addr_kernel<<<1, 128>>>(addr, addr_type, poi_emb, addr_W, addr_b);
    prep_kernel<<<2048, 256>>>(Whh_f, Whh_b, out_W);
    xp_kernel<<<dim3(32, 128, 2), 256>>>(loc_dense, time_dist, len, time_W, time_b,
                                         Wih_f, b_f, Wih_b, b_b);
    lstm_kernel<<<dim3(8, 8, 2), 256, LSTM_SMEM>>>(len);
    score_kernel<<<dim3(128, 128), 256>>>(len, comb_W);
    softmax_kernel<<<128, 256>>>(len, out);
}

// round 5
// speedup vs baseline: 1.1282x; 1.1282x over previous
#include <cuda_runtime.h>
#include <math.h>

#define B 128
#define T 1024
#define H 256
#define G4 1024   // 4*H

// ------------------- device scratch (static, zero-initialized) -------------------
__device__ float g_xp[(size_t)2 * T * B * G4];     // x@Wih.T + b, rows reordered (4*h+gate), [d][t][b][1024]
__device__ float g_hstore[(size_t)2 * T * B * H];  // recorded h, [d][t][b][h]
__device__ float g_WTT[2 * G4 * H];                // Whh reordered rows, row-major: [d][r'][k]
__device__ float g_outWT[512 * 32];                // out_W transposed: [k][j]
__device__ float g_hbuf[2 * 2 * B * H];            // ping-pong h state: [parity][d][b][h]
__device__ float g_c[2 * B * H];                   // cell state: [d][b][h]
__device__ float g_af[B * 32];                     // addr_feat
__device__ float g_scores[B * T];
__device__ int   g_cnt[16];                        // per-(dir,btile) step counters

__device__ __forceinline__ void ffma2(unsigned long long& d,
                                      unsigned long long a,
                                      unsigned long long b) {
    asm("fma.rn.f32x2 %0, %1, %2, %0;" : "+l"(d) : "l"(a), "l"(b));
}

// ------------------- clear state (per replay) -------------------
__global__ void clear_kernel() {
    int i = blockIdx.x * 256 + threadIdx.x;
    if (i < 2 * 2 * B * H) g_hbuf[i] = 0.0f;
    if (i < 2 * B * H)     g_c[i]    = 0.0f;
    if (i < 16)            g_cnt[i]  = 0;
}

// ------------------- weight prep: gate-interleaved rows, row-major -------------------
__global__ void prep_kernel(const float* __restrict__ Whh_f,
                            const float* __restrict__ Whh_b,
                            const float* __restrict__ out_W) {
    int idx = blockIdx.x * 256 + threadIdx.x;
    if (idx < 2 * G4 * H) {
        int k  = idx & 255;
        int rp = (idx >> 8) & 1023;   // reordered row r' = 4*jh + g
        int d  = idx >> 18;
        int g  = rp & 3, jh = rp >> 2;
        const float* Whh = d ? Whh_b : Whh_f;
        g_WTT[idx] = Whh[(g * 256 + jh) * H + k];
    }
    if (idx < 512 * 32) {
        int k = idx >> 5, j = idx & 31;
        g_outWT[idx] = out_W[j * 512 + k];
    }
}

// ------------------- addr_feat -------------------
__global__ void addr_kernel(const float* __restrict__ addr,
                            const int*   __restrict__ addr_type,
                            const float* __restrict__ poi_emb,
                            const float* __restrict__ addr_W,
                            const float* __restrict__ addr_b) {
    int b = threadIdx.x;  // 128
    float inp[4];
    inp[0] = addr[b];
    int at = addr_type[b];
    inp[1] = poi_emb[at * 3 + 0];
    inp[2] = poi_emb[at * 3 + 1];
    inp[3] = poi_emb[at * 3 + 2];
    for (int j = 0; j < 32; j++) {
        float a = addr_b[j];
        #pragma unroll
        for (int f = 0; f < 4; f++) a += addr_W[j * 4 + f] * inp[f];
        g_af[b * 32 + j] = a;
    }
}

// ------------------- xp = loc_seq @ Wih.T + b (reordered rows), active (b,t) only -------------------
__global__ void __launch_bounds__(256) xp_kernel(
    const float* __restrict__ loc_dense, const float* __restrict__ time_dist,
    const int* __restrict__ len, const float* __restrict__ time_W,
    const float* __restrict__ time_b,
    const float* __restrict__ Wih_f, const float* __restrict__ b_f,
    const float* __restrict__ Wih_b, const float* __restrict__ b_b) {
    int b = blockIdx.y, d = blockIdx.z;
    int t0 = blockIdx.x * 32;
    int n = len[b];
    if (t0 >= n) return;
    const float* Wih  = d ? Wih_b : Wih_f;
    const float* bias = d ? b_b  : b_f;

    __shared__ float loc19[32][19];
    int tid = threadIdx.x;
    for (int i = tid; i < 32 * 16; i += 256) {
        int tt = i >> 4, f = i & 15;
        loc19[tt][f] = loc_dense[((size_t)b * T + t0 + tt) * 16 + f];
    }
    if (tid < 96) {
        int tt = tid / 3, e = tid % 3;
        float acc = time_b[e];
        const float* tdp = &time_dist[((size_t)b * T + t0 + tt) * 8];
        #pragma unroll
        for (int f = 0; f < 8; f++) acc += time_W[e * 8 + f] * tdp[f];
        loc19[tt][16 + e] = acc;
    }
    __syncthreads();

    int j = tid;  // h index 0..255; owns reordered rows 4j..4j+3
    float w[4][19], bz[4];
    #pragma unroll
    for (int g = 0; g < 4; g++) {
        int orig = g * 256 + j;
        bz[g] = bias[orig];
        #pragma unroll
        for (int f = 0; f < 19; f++) w[g][f] = Wih[orig * 19 + f];
    }
    int tmax = min(32, n - t0);
    for (int tt = 0; tt < tmax; tt++) {
        float accs[4];
        #pragma unroll
        for (int g = 0; g < 4; g++) {
            float a = bz[g];
            #pragma unroll
            for (int f = 0; f < 19; f++) a += w[g][f] * loc19[tt][f];
            accs[g] = a;
        }
        float4 out4 = make_float4(accs[0], accs[1], accs[2], accs[3]);
        *(float4*)&g_xp[(((size_t)d * T + t0 + tt) * B + b) * G4 + j * 4] = out4;
    }
}

// ------------------- persistent bidirectional LSTM recurrence -------------------
// Grid (8 gate-tiles, 8 batch-tiles, 2 dirs) = 128 CTAs, all co-resident.
// CTA: 128 reordered gate rows x 16 batches; Whh tile resident in smem.
// Inner product uses packed f32x2 FMA paired over even/odd k.
// Group = 8 CTAs sharing (btile, dir); release/acquire counter barrier.
__global__ void __launch_bounds__(256, 1) lstm_kernel(const int* __restrict__ len) {
    extern __shared__ float smem[];
    float* sWT = smem;                    // [128][260]
    float* hT  = smem + 128 * 260;        // [16][260]
    float* pre = smem + 128 * 260 + 16 * 260;  // [16][132]

    int gx  = blockIdx.x;   // gate tile (128 reordered rows)
    int gy  = blockIdx.y;   // batch tile (16 batches)
    int dir = blockIdx.z;
    int tid = threadIdx.x;
    int b0  = gy * 16;
    int g0  = gx * 128;
    int h0  = gx * 32;
    int nloc = len[b0];     // tile max length (sorted descending)
    int* cnt = &g_cnt[dir * 8 + gy];

    // resident weight tile (coalesced read, padded smem write)
    const float* WTT = &g_WTT[((size_t)dir * G4 + g0) * 256];
    for (int e = tid; e < 128 * 256; e += 256) {
        int row = e >> 8, k = e & 255;
        sWT[row * 260 + k] = WTT[e];
    }
    __syncthreads();

    int tx = tid & 127;   // local row
    int ty = tid >> 7;    // batch half

    for (int i = 0; i < nloc; i++) {
        int s = dir ? (nloc - 1 - i) : i;
        int pin = i & 1, pout = pin ^ 1;

        // prefetch xp for this step (independent of h) BEFORE the wait
        float xpre[8];
        {
            size_t xb = (((size_t)dir * T + s) * B + b0 + ty * 8) * G4 + g0 + tx;
            #pragma unroll
            for (int j = 0; j < 8; j++) xpre[j] = g_xp[xb + (size_t)j * G4];
        }

        // wait for previous step of whole group (all threads poll)
        if (i > 0) {
            int target = 8 * i, v;
            do {
                asm volatile("ld.acquire.gpu.global.s32 %0, [%1];"
                             : "=r"(v) : "l"(cnt) : "memory");
            } while (v < target);
        }

        // stage h(t-1) into smem (L2 loads; written by peer SMs)
        {
            const float* hg = &g_hbuf[((size_t)(pin * 2 + dir) * B + b0) * H];
            #pragma unroll
            for (int p = 0; p < 4; p++) {
                int e = tid + 256 * p;
                int b = e >> 6, k4 = (e & 63) * 4;
                float4 v4 = __ldcg((const float4*)&hg[b * H + k4]);
                *(float4*)&hT[b * 260 + k4] = v4;
            }
        }
        __syncthreads();

        // gate GEMM: packed f32x2, pairs over (even k, odd k)
        unsigned long long acc[8];
        #pragma unroll
        for (int j = 0; j < 8; j++) acc[j] = 0ULL;
        {
            const float* wrow = &sWT[tx * 260];
            const float* hbase = &hT[ty * 8 * 260];
            #pragma unroll 8
            for (int k = 0; k < 256; k += 4) {
                ulonglong2 w2 = *(const ulonglong2*)(wrow + k);
                #pragma unroll
                for (int j = 0; j < 8; j++) {
                    ulonglong2 h2 = *(const ulonglong2*)(hbase + j * 260 + k);
                    ffma2(acc[j], w2.x, h2.x);
                    ffma2(acc[j], w2.y, h2.y);
                }
            }
        }
        #pragma unroll
        for (int j = 0; j < 8; j++) {
            float2 f2 = *reinterpret_cast<float2*>(&acc[j]);
            pre[(ty * 8 + j) * 132 + tx] = f2.x + f2.y + xpre[j];
        }
        __syncthreads();

        // epilogue: 32 h x 16 b = 512 outputs, 2 per thread
        #pragma unroll
        for (int q = 0; q < 2; q++) {
            int o  = tid + q * 256;
            int hl = o & 31, b2 = o >> 5;
            int b  = b0 + b2;
            size_t ho = ((size_t)(pout * 2 + dir) * B + b) * H + h0 + hl;
            if (s < len[b]) {
                float4 g4 = *(const float4*)&pre[b2 * 132 + 4 * hl];
                size_t ci = ((size_t)dir * B + b) * H + h0 + hl;
                float cold = g_c[ci];
                float si = 1.f / (1.f + expf(-g4.x));
                float sf = 1.f / (1.f + expf(-g4.y));
                float so = 1.f / (1.f + expf(-g4.w));
                float cn = sf * cold + si * tanhf(g4.z);
                float hn = so * tanhf(cn);
                g_c[ci] = cn;
                g_hbuf[ho] = hn;
                g_hstore[(((size_t)dir * T + s) * B + b) * H + h0 + hl] = hn;
            } else {
                g_hbuf[ho] = hT[b2 * 260 + h0 + hl];  // carry forward
            }
        }
        __syncthreads();
        if (tid == 0)
            asm volatile("red.release.gpu.global.add.s32 [%0], %1;"
                         :: "l"(cnt), "r"(1) : "memory");
    }
}

// ------------------- scores: comb_W . tanh(out_W @ [hf;hb] + addr_feat) -------------------
__global__ void __launch_bounds__(256) score_kernel(const int* __restrict__ len,
                                                    const float* __restrict__ comb_W) {
    int b = blockIdx.y;
    int t0 = blockIdx.x * 8;
    int n = len[b];
    if (t0 >= n) return;
    int w = threadIdx.x >> 5, lane = threadIdx.x & 31;
    int t = t0 + w;
    if (t >= n) return;
    float a0 = g_af[b * 32 + lane], a1 = 0.f, a2 = 0.f, a3 = 0.f;
    const float* hf = &g_hstore[(((size_t)0 * T + t) * B + b) * H];
    const float* hb = &g_hstore[(((size_t)1 * T + t) * B + b) * H];
    #pragma unroll 8
    for (int k = 0; k < 256; k += 4) {
        float4 h4 = *(const float4*)&hf[k];
        a0 = fmaf(g_outWT[(k + 0) * 32 + lane], h4.x, a0);
        a1 = fmaf(g_outWT[(k + 1) * 32 + lane], h4.y, a1);
        a2 = fmaf(g_outWT[(k + 2) * 32 + lane], h4.z, a2);
        a3 = fmaf(g_outWT[(k + 3) * 32 + lane], h4.w, a3);
    }
    #pragma unroll 8
    for (int k = 0; k < 256; k += 4) {
        float4 h4 = *(const float4*)&hb[k];
        a0 = fmaf(g_outWT[(256 + k + 0) * 32 + lane], h4.x, a0);
        a1 = fmaf(g_outWT[(256 + k + 1) * 32 + lane], h4.y, a1);
        a2 = fmaf(g_outWT[(256 + k + 2) * 32 + lane], h4.z, a2);
        a3 = fmaf(g_outWT[(256 + k + 3) * 32 + lane], h4.w, a3);
    }
    float v = tanhf(a0 + a1 + a2 + a3) * comb_W[lane];
    #pragma unroll
    for (int off = 16; off; off >>= 1) v += __shfl_down_sync(0xffffffffu, v, off);
    if (lane == 0) g_scores[b * T + t] = v;
}

// ------------------- masked log-softmax over T -------------------
__global__ void __launch_bounds__(256) softmax_kernel(const int* __restrict__ len,
                                                      float* __restrict__ out) {
    int b = blockIdx.x;
    int n = len[b];
    int tid = threadIdx.x;
    __shared__ float red[256];
    float m = -1e30f;
    for (int t = tid; t < n; t += 256) m = fmaxf(m, g_scores[b * T + t]);
    red[tid] = m; __syncthreads();
    for (int st = 128; st; st >>= 1) {
        if (tid < st) red[tid] = fmaxf(red[tid], red[tid + st]);
        __syncthreads();
    }
    m = red[0]; __syncthreads();
    float sum = 0.f;
    for (int t = tid; t < n; t += 256) sum += expf(g_scores[b * T + t] - m);
    red[tid] = sum; __syncthreads();
    for (int st = 128; st; st >>= 1) {
        if (tid < st) red[tid] += red[tid + st];
        __syncthreads();
    }
    float lse = m + logf(red[0]);
    for (int t = tid; t < T; t += 256)
        out[b * T + t] = (t < n) ? (g_scores[b * T + t] - lse) : 0.0f;
}

// ------------------- launch -------------------
extern "C" void kernel_launch(void* const* d_in, const int* in_sizes, int n_in,
                              void* d_out, int out_size) {
    (void)in_sizes; (void)n_in; (void)out_size;
    const float* addr      = (const float*)d_in[0];
    const int*   addr_type = (const int*)  d_in[1];
    const float* loc_dense = (const float*)d_in[2];
    const float* time_dist = (const float*)d_in[3];
    const int*   len       = (const int*)  d_in[4];
    const float* poi_emb   = (const float*)d_in[5];
    const float* time_W    = (const float*)d_in[6];
    const float* time_b    = (const float*)d_in[7];
    const float* addr_W    = (const float*)d_in[8];
    const float* addr_b    = (const float*)d_in[9];
    const float* Wih_f     = (const float*)d_in[10];
    const float* Whh_f     = (const float*)d_in[11];
    const float* b_f       = (const float*)d_in[12];
    const float* Wih_b     = (const float*)d_in[13];
    const float* Whh_b     = (const float*)d_in[14];
    const float* b_b       = (const float*)d_in[15];
    const float* out_W     = (const float*)d_in[16];
    const float* comb_W    = (const float*)d_in[17];
    float* out = (float*)d_out;

    static int smem_set = 0;
    const int LSTM_SMEM = (128 * 260 + 16 * 260 + 16 * 132) * 4;  // 158208 B
    if (!smem_set) {
        cudaFuncSetAttribute(lstm_kernel,
                             cudaFuncAttributeMaxDynamicSharedMemorySize, LSTM_SMEM);
        smem_set = 1;
    }

    clear_kernel<<<512, 256>>>();
    addr_kernel<<<1, 128>>>(addr, addr_type, poi_emb, addr_W, addr_b);
    prep_kernel<<<2048, 256>>>(Whh_f, Whh_b, out_W);
    xp_kernel<<<dim3(32, 128, 2), 256>>>(loc_dense, time_dist, len, time_W, time_b,
                                         Wih_f, b_f, Wih_b, b_b);
    lstm_kernel<<<dim3(8, 8, 2), 256, LSTM_SMEM>>>(len);
    score_kernel<<<dim3(128, 128), 256>>>(len, comb_W);
    softmax_kernel<<<128, 256>>>(len, out);
}

// round 6
// speedup vs baseline: 1.1863x; 1.0515x over previous
#include <cuda_runtime.h>
#include <math.h>

#define B 128
#define T 1024
#define H 256
#define G4 1024   // 4*H

// ------------------- device scratch (static, zero-initialized) -------------------
__device__ float g_xp[(size_t)2 * T * B * G4];     // x@Wih.T + b, rows reordered (4*h+gate), [d][t][b][1024]
__device__ float g_hstore[(size_t)2 * T * B * H];  // recorded h, [d][t][b][h]
__device__ float g_WTT[2 * G4 * H];                // Whh reordered rows, row-major: [d][r'][k]
__device__ float g_outWT[512 * 32];                // out_W transposed: [k][j]
__device__ float g_hbuf[2 * 2 * B * H];            // ping-pong h state: [parity][d][b][h]
__device__ float g_c[2 * B * H];                   // cell state: [d][b][h]
__device__ float g_af[B * 32];                     // addr_feat
__device__ float g_scores[B * T];
__device__ int   g_cnt[16];                        // per-(dir,btile) step counters

__device__ __forceinline__ void ffma2(unsigned long long& d,
                                      unsigned long long a,
                                      unsigned long long b) {
    asm("fma.rn.f32x2 %0, %1, %2, %0;" : "+l"(d) : "l"(a), "l"(b));
}
__device__ __forceinline__ float sigmoid_fast(float x) {
    float e = __expf(-x);
    float r;
    asm("rcp.approx.f32 %0, %1;" : "=f"(r) : "f"(1.0f + e));
    return r;
}
__device__ __forceinline__ float tanh_fast(float x) {
    float r;
    asm("tanh.approx.f32 %0, %1;" : "=f"(r) : "f"(x));
    return r;
}

// ------------------- clear state (per replay) -------------------
__global__ void clear_kernel() {
    int i = blockIdx.x * 256 + threadIdx.x;
    if (i < 2 * 2 * B * H) g_hbuf[i] = 0.0f;
    if (i < 2 * B * H)     g_c[i]    = 0.0f;
    if (i < 16)            g_cnt[i]  = 0;
}

// ------------------- weight prep: gate-interleaved rows, row-major -------------------
__global__ void prep_kernel(const float* __restrict__ Whh_f,
                            const float* __restrict__ Whh_b,
                            const float* __restrict__ out_W) {
    int idx = blockIdx.x * 256 + threadIdx.x;
    if (idx < 2 * G4 * H) {
        int k  = idx & 255;
        int rp = (idx >> 8) & 1023;   // reordered row r' = 4*jh + g
        int d  = idx >> 18;
        int g  = rp & 3, jh = rp >> 2;
        const float* Whh = d ? Whh_b : Whh_f;
        g_WTT[idx] = Whh[(g * 256 + jh) * H + k];
    }
    if (idx < 512 * 32) {
        int k = idx >> 5, j = idx & 31;
        g_outWT[idx] = out_W[j * 512 + k];
    }
}

// ------------------- addr_feat -------------------
__global__ void addr_kernel(const float* __restrict__ addr,
                            const int*   __restrict__ addr_type,
                            const float* __restrict__ poi_emb,
                            const float* __restrict__ addr_W,
                            const float* __restrict__ addr_b) {
    int b = threadIdx.x;  // 128
    float inp[4];
    inp[0] = addr[b];
    int at = addr_type[b];
    inp[1] = poi_emb[at * 3 + 0];
    inp[2] = poi_emb[at * 3 + 1];
    inp[3] = poi_emb[at * 3 + 2];
    for (int j = 0; j < 32; j++) {
        float a = addr_b[j];
        #pragma unroll
        for (int f = 0; f < 4; f++) a += addr_W[j * 4 + f] * inp[f];
        g_af[b * 32 + j] = a;
    }
}

// ------------------- xp = loc_seq @ Wih.T + b (reordered rows), active (b,t) only -------------------
__global__ void __launch_bounds__(256) xp_kernel(
    const float* __restrict__ loc_dense, const float* __restrict__ time_dist,
    const int* __restrict__ len, const float* __restrict__ time_W,
    const float* __restrict__ time_b,
    const float* __restrict__ Wih_f, const float* __restrict__ b_f,
    const float* __restrict__ Wih_b, const float* __restrict__ b_b) {
    int b = blockIdx.y, d = blockIdx.z;
    int t0 = blockIdx.x * 32;
    int n = len[b];
    if (t0 >= n) return;
    const float* Wih  = d ? Wih_b : Wih_f;
    const float* bias = d ? b_b  : b_f;

    __shared__ float loc19[32][19];
    int tid = threadIdx.x;
    for (int i = tid; i < 32 * 16; i += 256) {
        int tt = i >> 4, f = i & 15;
        loc19[tt][f] = loc_dense[((size_t)b * T + t0 + tt) * 16 + f];
    }
    if (tid < 96) {
        int tt = tid / 3, e = tid % 3;
        float acc = time_b[e];
        const float* tdp = &time_dist[((size_t)b * T + t0 + tt) * 8];
        #pragma unroll
        for (int f = 0; f < 8; f++) acc += time_W[e * 8 + f] * tdp[f];
        loc19[tt][16 + e] = acc;
    }
    __syncthreads();

    int j = tid;  // h index 0..255; owns reordered rows 4j..4j+3
    float w[4][19], bz[4];
    #pragma unroll
    for (int g = 0; g < 4; g++) {
        int orig = g * 256 + j;
        bz[g] = bias[orig];
        #pragma unroll
        for (int f = 0; f < 19; f++) w[g][f] = Wih[orig * 19 + f];
    }
    int tmax = min(32, n - t0);
    for (int tt = 0; tt < tmax; tt++) {
        float accs[4];
        #pragma unroll
        for (int g = 0; g < 4; g++) {
            float a = bz[g];
            #pragma unroll
            for (int f = 0; f < 19; f++) a += w[g][f] * loc19[tt][f];
            accs[g] = a;
        }
        float4 out4 = make_float4(accs[0], accs[1], accs[2], accs[3]);
        *(float4*)&g_xp[(((size_t)d * T + t0 + tt) * B + b) * G4 + j * 4] = out4;
    }
}

// ------------------- persistent bidirectional LSTM recurrence -------------------
// Grid (8 gate-tiles, 8 batch-tiles, 2 dirs) = 128 CTAs, all co-resident.
// 512 threads/CTA: thread = (tx=row 0..127, ty=batch-half, kz=k-half).
// Each thread reduces 128 k for 8 batches; k-halves summed in epilogue.
// Group = 8 CTAs sharing (btile, dir); release/acquire counter barrier.
__global__ void __launch_bounds__(512, 1) lstm_kernel(const int* __restrict__ len) {
    extern __shared__ float smem[];
    float* sWT = smem;                         // [128][260]
    float* hT  = smem + 128 * 260;             // [16][260]
    float* pre = smem + 128 * 260 + 16 * 260;  // [2(kz)][16][132]

    int gx  = blockIdx.x;   // gate tile (128 reordered rows)
    int gy  = blockIdx.y;   // batch tile (16 batches)
    int dir = blockIdx.z;
    int tid = threadIdx.x;
    int b0  = gy * 16;
    int g0  = gx * 128;
    int h0  = gx * 32;
    int nloc = len[b0];     // tile max length (sorted descending)
    int* cnt = &g_cnt[dir * 8 + gy];

    // resident weight tile (coalesced read, padded smem write)
    const float* WTT = &g_WTT[((size_t)dir * G4 + g0) * 256];
    for (int e = tid; e < 128 * 256; e += 512) {
        int row = e >> 8, k = e & 255;
        sWT[row * 260 + k] = WTT[e];
    }
    __syncthreads();

    int tx = tid & 127;          // local row
    int q  = tid >> 7;           // 0..3
    int ty = q & 1;              // batch half
    int kz = q >> 1;             // k half

    for (int i = 0; i < nloc; i++) {
        int s = dir ? (nloc - 1 - i) : i;
        int pin = i & 1, pout = pin ^ 1;

        // prefetch xp for this step (independent of h) BEFORE the wait (kz=0 only)
        float xpre[8];
        if (kz == 0) {
            size_t xb = (((size_t)dir * T + s) * B + b0 + ty * 8) * G4 + g0 + tx;
            #pragma unroll
            for (int j = 0; j < 8; j++) xpre[j] = g_xp[xb + (size_t)j * G4];
        }

        // wait for previous step of whole group
        if (i > 0) {
            int target = 8 * i, v;
            do {
                asm volatile("ld.acquire.gpu.global.s32 %0, [%1];"
                             : "=r"(v) : "l"(cnt) : "memory");
            } while (v < target);
        }

        // stage h(t-1) into smem (L2 loads; written by peer SMs)
        {
            const float* hg = &g_hbuf[((size_t)(pin * 2 + dir) * B + b0) * H];
            #pragma unroll
            for (int p = 0; p < 2; p++) {
                int e = tid + 512 * p;
                int b = e >> 6, k4 = (e & 63) * 4;
                float4 v4 = __ldcg((const float4*)&hg[b * H + k4]);
                *(float4*)&hT[b * 260 + k4] = v4;
            }
        }
        __syncthreads();

        // gate GEMM: packed f32x2, half the k range per thread
        unsigned long long acc[8];
        #pragma unroll
        for (int j = 0; j < 8; j++) acc[j] = 0ULL;
        {
            const float* wrow  = &sWT[tx * 260 + kz * 128];
            const float* hbase = &hT[ty * 8 * 260 + kz * 128];
            #pragma unroll 8
            for (int k = 0; k < 128; k += 4) {
                ulonglong2 w2 = *(const ulonglong2*)(wrow + k);
                #pragma unroll
                for (int j = 0; j < 8; j++) {
                    ulonglong2 h2 = *(const ulonglong2*)(hbase + j * 260 + k);
                    ffma2(acc[j], w2.x, h2.x);
                    ffma2(acc[j], w2.y, h2.y);
                }
            }
        }
        #pragma unroll
        for (int j = 0; j < 8; j++) {
            float2 f2 = *reinterpret_cast<float2*>(&acc[j]);
            float v = f2.x + f2.y;
            if (kz == 0) v += xpre[j];
            pre[(kz * 16 + ty * 8 + j) * 132 + tx] = v;
        }
        __syncthreads();

        // epilogue: 512 cells, 1 per thread
        {
            int hl = tid & 31, b2 = tid >> 5;
            int b  = b0 + b2;
            size_t ho = ((size_t)(pout * 2 + dir) * B + b) * H + h0 + hl;
            float hn;
            if (s < len[b]) {
                float4 gA = *(const float4*)&pre[b2 * 132 + 4 * hl];
                float4 gB = *(const float4*)&pre[(16 + b2) * 132 + 4 * hl];
                float gi = gA.x + gB.x, gf = gA.y + gB.y;
                float gg = gA.z + gB.z, go = gA.w + gB.w;
                size_t ci = ((size_t)dir * B + b) * H + h0 + hl;
                float cold = g_c[ci];
                float cn = sigmoid_fast(gf) * cold + sigmoid_fast(gi) * tanh_fast(gg);
                hn = sigmoid_fast(go) * tanh_fast(cn);
                g_c[ci] = cn;
                g_hstore[(((size_t)dir * T + s) * B + b) * H + h0 + hl] = hn;
            } else {
                hn = hT[b2 * 260 + h0 + hl];  // carry forward
            }
            g_hbuf[ho] = hn;
        }
        __syncthreads();
        if (tid == 0)
            asm volatile("red.release.gpu.global.add.s32 [%0], %1;"
                         :: "l"(cnt), "r"(1) : "memory");
    }
}

// ------------------- scores: comb_W . tanh(out_W @ [hf;hb] + addr_feat) -------------------
__global__ void __launch_bounds__(256) score_kernel(const int* __restrict__ len,
                                                    const float* __restrict__ comb_W) {
    int b = blockIdx.y;
    int t0 = blockIdx.x * 8;
    int n = len[b];
    if (t0 >= n) return;
    int w = threadIdx.x >> 5, lane = threadIdx.x & 31;
    int t = t0 + w;
    if (t >= n) return;
    float a0 = g_af[b * 32 + lane], a1 = 0.f, a2 = 0.f, a3 = 0.f;
    const float* hf = &g_hstore[(((size_t)0 * T + t) * B + b) * H];
    const float* hb = &g_hstore[(((size_t)1 * T + t) * B + b) * H];
    #pragma unroll 8
    for (int k = 0; k < 256; k += 4) {
        float4 h4 = *(const float4*)&hf[k];
        a0 = fmaf(g_outWT[(k + 0) * 32 + lane], h4.x, a0);
        a1 = fmaf(g_outWT[(k + 1) * 32 + lane], h4.y, a1);
        a2 = fmaf(g_outWT[(k + 2) * 32 + lane], h4.z, a2);
        a3 = fmaf(g_outWT[(k + 3) * 32 + lane], h4.w, a3);
    }
    #pragma unroll 8
    for (int k = 0; k < 256; k += 4) {
        float4 h4 = *(const float4*)&hb[k];
        a0 = fmaf(g_outWT[(256 + k + 0) * 32 + lane], h4.x, a0);
        a1 = fmaf(g_outWT[(256 + k + 1) * 32 + lane], h4.y, a1);
        a2 = fmaf(g_outWT[(256 + k + 2) * 32 + lane], h4.z, a2);
        a3 = fmaf(g_outWT[(256 + k + 3) * 32 + lane], h4.w, a3);
    }
    float v = tanhf(a0 + a1 + a2 + a3) * comb_W[lane];
    #pragma unroll
    for (int off = 16; off; off >>= 1) v += __shfl_down_sync(0xffffffffu, v, off);
    if (lane == 0) g_scores[b * T + t] = v;
}

// ------------------- masked log-softmax over T -------------------
__global__ void __launch_bounds__(256) softmax_kernel(const int* __restrict__ len,
                                                      float* __restrict__ out) {
    int b = blockIdx.x;
    int n = len[b];
    int tid = threadIdx.x;
    __shared__ float red[256];
    float m = -1e30f;
    for (int t = tid; t < n; t += 256) m = fmaxf(m, g_scores[b * T + t]);
    red[tid] = m; __syncthreads();
    for (int st = 128; st; st >>= 1) {
        if (tid < st) red[tid] = fmaxf(red[tid], red[tid + st]);
        __syncthreads();
    }
    m = red[0]; __syncthreads();
    float sum = 0.f;
    for (int t = tid; t < n; t += 256) sum += expf(g_scores[b * T + t] - m);
    red[tid] = sum; __syncthreads();
    for (int st = 128; st; st >>= 1) {
        if (tid < st) red[tid] += red[tid + st];
        __syncthreads();
    }
    float lse = m + logf(red[0]);
    for (int t = tid; t < T; t += 256)
        out[b * T + t] = (t < n) ? (g_scores[b * T + t] - lse) : 0.0f;
}

// ------------------- launch -------------------
extern "C" void kernel_launch(void* const* d_in, const int* in_sizes, int n_in,
                              void* d_out, int out_size) {
    (void)in_sizes; (void)n_in; (void)out_size;
    const float* addr      = (const float*)d_in[0];
    const int*   addr_type = (const int*)  d_in[1];
    const float* loc_dense = (const float*)d_in[2];
    const float* time_dist = (const float*)d_in[3];
    const int*   len       = (const int*)  d_in[4];
    const float* poi_emb   = (const float*)d_in[5];
    const float* time_W    = (const float*)d_in[6];
    const float* time_b    = (const float*)d_in[7];
    const float* addr_W    = (const float*)d_in[8];
    const float* addr_b    = (const float*)d_in[9];
    const float* Wih_f     = (const float*)d_in[10];
    const float* Whh_f     = (const float*)d_in[11];
    const float* b_f       = (const float*)d_in[12];
    const float* Wih_b     = (const float*)d_in[13];
    const float* Whh_b     = (const float*)d_in[14];
    const float* b_b       = (const float*)d_in[15];
    const float* out_W     = (const float*)d_in[16];
    const float* comb_W    = (const float*)d_in[17];
    float* out = (float*)d_out;

    static int smem_set = 0;
    const int LSTM_SMEM = (128 * 260 + 16 * 260 + 2 * 16 * 132) * 4;  // 166656 B
    if (!smem_set) {
        cudaFuncSetAttribute(lstm_kernel,
                             cudaFuncAttributeMaxDynamicSharedMemorySize, LSTM_SMEM);
        smem_set = 1;
    }

    clear_kernel<<<512, 256>>>();
    addr_kernel<<<1, 128>>>(addr, addr_type, poi_emb, addr_W, addr_b);
    prep_kernel<<<2048, 256>>>(Whh_f, Whh_b, out_W);
    xp_kernel<<<dim3(32, 128, 2), 256>>>(loc_dense, time_dist, len, time_W, time_b,
                                         Wih_f, b_f, Wih_b, b_b);
    lstm_kernel<<<dim3(8, 8, 2), 512, LSTM_SMEM>>>(len);
    score_kernel<<<dim3(128, 128), 256>>>(len, comb_W);
    softmax_kernel<<<128, 256>>>(len, out);
}